// round 6
// baseline (speedup 1.0000x reference)
#include <cuda_runtime.h>
#include <cuda_bf16.h>
#include <cstdint>

// VectorQuantizer: N=262144 rows, D=64, K=1024 codes, fp32.
//
// Round 6: single-sweep kernel (R4/R5 never ran: container infra failures).
// Diff minimized vs the last PASSING launch structure (R3): exactly two
// launches (main + loss), no nop padding.
//
// SINGLE bf16 tensor-core sweep + per-(row, 32-code-group) minima in smem +
// exact fp32 rescoring of groups within margin of the row min.
//   - gemm scores d~ = Se - 2*M~ (Sx shift is argmin-invariant)
//   - group granularity makes candidate capture overflow-free (no atomics)
//   - rescore: bit-exact reference-rounding emulation (same as passing R2/R3):
//     M = serial ascending-d fmaf chain, t = Sx + Se, d = fmaf(-2, M, t),
//     argmin strict < ascending k (first-index ties).

#define VQ_N       262144
#define VQ_D       64
#define VQ_K       1024
#define VQ_TPB     256
#define VQ_ROWS_PB 128                    // 8 warps x 16 rows
#define VQ_GRID    (VQ_N / VQ_ROWS_PB)   // 2048 blocks
#define VQ_CHUNK   128                   // codes staged per chunk
#define VQ_NCHUNK  (VQ_K / VQ_CHUNK)     // 8
#define VQ_EPAD    72                    // padded bf16 row (144B)
#define VQ_GRP     32                    // codes per candidate group
#define VQ_NGRP    (VQ_K / VQ_GRP)       // 32 groups
#define VQ_MARGIN  1e-3f

__device__ float g_vq_partial[VQ_GRID];

__device__ __forceinline__ uint32_t pack_bf16x2(float lo, float hi) {
    __nv_bfloat162 h = __float22bfloat162_rn(make_float2(lo, hi));
    return *reinterpret_cast<uint32_t*>(&h);
}

__device__ __forceinline__ void mma_bf16(float& c0, float& c1, float& c2, float& c3,
                                         uint32_t a0, uint32_t a1, uint32_t a2, uint32_t a3,
                                         uint32_t b0, uint32_t b1) {
    asm volatile(
        "mma.sync.aligned.m16n8k16.row.col.f32.bf16.bf16.f32 "
        "{%0,%1,%2,%3},{%4,%5,%6,%7},{%8,%9},{%0,%1,%2,%3};"
        : "+f"(c0), "+f"(c1), "+f"(c2), "+f"(c3)
        : "r"(a0), "r"(a1), "r"(a2), "r"(a3), "r"(b0), "r"(b1));
}

__device__ __forceinline__ void ldsm_x4(uint32_t& r0, uint32_t& r1, uint32_t& r2, uint32_t& r3,
                                        uint32_t addr) {
    asm volatile("ldmatrix.sync.aligned.m8n8.x4.shared.b16 {%0,%1,%2,%3}, [%4];"
                 : "=r"(r0), "=r"(r1), "=r"(r2), "=r"(r3) : "r"(addr));
}

__global__ void __launch_bounds__(VQ_TPB, 2)
vq_main_kernel(const float* __restrict__ x,
               const float* __restrict__ cb,
               float* __restrict__ out,
               int write_q)
{
    __shared__ __nv_bfloat16 s_e[VQ_CHUNK * VQ_EPAD];      // 18 KB bf16 chunk
    __shared__ float s_Se[VQ_K];                           // exact serial-fmaf norms
    __shared__ float s_gmin[VQ_ROWS_PB][VQ_NGRP];          // 16 KB group minima
    __shared__ int   s_win[VQ_ROWS_PB];
    __shared__ float s_red[VQ_TPB];

    const int tid  = threadIdx.x;
    const int wid  = tid >> 5;
    const int lane = tid & 31;
    const int g    = lane >> 2;
    const int tg   = lane & 3;
    const int rowbase = blockIdx.x * VQ_ROWS_PB;
    const int r0i = wid * 16 + g;
    const int r1i = r0i + 8;

    // ---- exact Se (serial ascending fmaf; must match rescore arithmetic) ----
    #pragma unroll
    for (int c = 0; c < VQ_K / VQ_TPB; c++) {
        int code = tid + c * VQ_TPB;
        const float4* e4 = reinterpret_cast<const float4*>(cb + (size_t)code * VQ_D);
        float s = 0.0f;
        #pragma unroll
        for (int i = 0; i < VQ_D / 4; i++) {
            float4 q = e4[i];
            s = fmaf(q.x, q.x, s); s = fmaf(q.y, q.y, s);
            s = fmaf(q.z, q.z, s); s = fmaf(q.w, q.w, s);
        }
        s_Se[code] = s;
    }

    // ---- A fragments: warp's 16 rows (g, g+8) as bf16, kept in regs ----
    uint32_t afr[4][4];
    {
        const float* xr0 = x + (size_t)(rowbase + r0i) * VQ_D;
        const float* xr1 = xr0 + 8 * VQ_D;
        #pragma unroll
        for (int kt = 0; kt < 4; kt++) {
            int c = kt * 16 + 2 * tg;
            afr[kt][0] = pack_bf16x2(xr0[c],     xr0[c + 1]);
            afr[kt][1] = pack_bf16x2(xr1[c],     xr1[c + 1]);
            afr[kt][2] = pack_bf16x2(xr0[c + 8], xr0[c + 9]);
            afr[kt][3] = pack_bf16x2(xr1[c + 8], xr1[c + 9]);
        }
    }

    const uint32_t s_e_base = (uint32_t)__cvta_generic_to_shared(s_e);
    const uint32_t lds_lane = (uint32_t)((lane & 7) * VQ_EPAD * 2 + (lane >> 3) * 16);

    // ================= SINGLE SWEEP: gemm + group minima =================
    for (int ch = 0; ch < VQ_NCHUNK; ch++) {
        const int c0 = ch * VQ_CHUNK;
        __syncthreads();
        {   // stage chunk as bf16 (code tid/2, half (tid&1)*32)
            int code = (tid >> 1), half = (tid & 1) * 32;
            const float4* src = reinterpret_cast<const float4*>(
                cb + (size_t)(c0 + code) * VQ_D + half);
            uint32_t* dst = reinterpret_cast<uint32_t*>(s_e + code * VQ_EPAD + half);
            #pragma unroll
            for (int i = 0; i < 8; i++) {
                float4 v = src[i];
                dst[2 * i]     = pack_bf16x2(v.x, v.y);
                dst[2 * i + 1] = pack_bf16x2(v.z, v.w);
            }
        }
        __syncthreads();

        #pragma unroll
        for (int q = 0; q < VQ_CHUNK / VQ_GRP; q++) {     // 4 groups per chunk
            float gm0 = 3.0e38f, gm1 = 3.0e38f;
            #pragma unroll
            for (int j = 0; j < 4; j++) {                 // 4 n-tiles per group
                const int nt = q * 4 + j;
                uint32_t base = s_e_base + (uint32_t)(nt * 8 * VQ_EPAD * 2) + lds_lane;
                uint32_t b0, b1, b2, b3, b4, b5, b6, b7;
                ldsm_x4(b0, b1, b2, b3, base);
                ldsm_x4(b4, b5, b6, b7, base + 64);
                float cA0 = 0.f, cA1 = 0.f, cA2 = 0.f, cA3 = 0.f;
                float cB0 = 0.f, cB1 = 0.f, cB2 = 0.f, cB3 = 0.f;
                mma_bf16(cA0, cA1, cA2, cA3, afr[0][0], afr[0][1], afr[0][2], afr[0][3], b0, b1);
                mma_bf16(cB0, cB1, cB2, cB3, afr[2][0], afr[2][1], afr[2][2], afr[2][3], b4, b5);
                mma_bf16(cA0, cA1, cA2, cA3, afr[1][0], afr[1][1], afr[1][2], afr[1][3], b2, b3);
                mma_bf16(cB0, cB1, cB2, cB3, afr[3][0], afr[3][1], afr[3][2], afr[3][3], b6, b7);
                float2 se = *reinterpret_cast<const float2*>(&s_Se[c0 + nt * 8 + 2 * tg]);
                float d0 = fmaf(-2.f, cA0, fmaf(-2.f, cB0, se.x));
                float d1 = fmaf(-2.f, cA1, fmaf(-2.f, cB1, se.y));
                float d2 = fmaf(-2.f, cA2, fmaf(-2.f, cB2, se.x));
                float d3 = fmaf(-2.f, cA3, fmaf(-2.f, cB3, se.y));
                gm0 = fminf(gm0, fminf(d0, d1));
                gm1 = fminf(gm1, fminf(d2, d3));
            }
            // reduce group min across the 4 tg-lanes of each row
            gm0 = fminf(gm0, __shfl_xor_sync(0xffffffffu, gm0, 1));
            gm0 = fminf(gm0, __shfl_xor_sync(0xffffffffu, gm0, 2));
            gm1 = fminf(gm1, __shfl_xor_sync(0xffffffffu, gm1, 1));
            gm1 = fminf(gm1, __shfl_xor_sync(0xffffffffu, gm1, 2));
            if (tg == 0) {
                const int grp = ch * 4 + q;
                s_gmin[r0i][grp] = gm0;
                s_gmin[r1i][grp] = gm1;
            }
        }
    }
    __syncthreads();

    // ======== exact rescore: thread 0..127 -> one row; groups within margin ====
    if (tid < VQ_ROWS_PB) {
        const int row = rowbase + tid;
        float4 xr[VQ_D / 4];
        const float4* xp = reinterpret_cast<const float4*>(x + (size_t)row * VQ_D);
        float Sx = 0.0f;
        #pragma unroll
        for (int i = 0; i < VQ_D / 4; i++) {
            float4 v = xp[i];
            xr[i] = v;
            Sx = fmaf(v.x, v.x, Sx); Sx = fmaf(v.y, v.y, Sx);
            Sx = fmaf(v.z, v.z, Sx); Sx = fmaf(v.w, v.w, Sx);
        }
        // fast row min over the 32 group minima
        float rowmin = 3.0e38f;
        const float4* gm4 = reinterpret_cast<const float4*>(&s_gmin[tid][0]);
        #pragma unroll
        for (int i = 0; i < VQ_NGRP / 4; i++) {
            float4 v = gm4[i];
            rowmin = fminf(rowmin, fminf(fminf(v.x, v.y), fminf(v.z, v.w)));
        }
        const float thr = rowmin + VQ_MARGIN;

        float best = 3.0e38f;
        int   bidx = 0;
        for (int grp = 0; grp < VQ_NGRP; grp++) {
            if (s_gmin[tid][grp] > thr) continue;
            const int k0 = grp * VQ_GRP;
            // exact rescore of the group's 32 codes, 4-wide ILP chains
            #pragma unroll 1
            for (int k = k0; k < k0 + VQ_GRP; k += 4) {
                const float4* e0 = reinterpret_cast<const float4*>(cb + (size_t)(k + 0) * VQ_D);
                const float4* e1 = reinterpret_cast<const float4*>(cb + (size_t)(k + 1) * VQ_D);
                const float4* e2 = reinterpret_cast<const float4*>(cb + (size_t)(k + 2) * VQ_D);
                const float4* e3 = reinterpret_cast<const float4*>(cb + (size_t)(k + 3) * VQ_D);
                float m0 = 0.f, m1 = 0.f, m2 = 0.f, m3 = 0.f;
                #pragma unroll
                for (int i = 0; i < VQ_D / 4; i++) {
                    float4 xv = xr[i];
                    float4 q0 = e0[i], q1 = e1[i], q2 = e2[i], q3 = e3[i];
                    m0 = fmaf(xv.x, q0.x, m0); m0 = fmaf(xv.y, q0.y, m0);
                    m0 = fmaf(xv.z, q0.z, m0); m0 = fmaf(xv.w, q0.w, m0);
                    m1 = fmaf(xv.x, q1.x, m1); m1 = fmaf(xv.y, q1.y, m1);
                    m1 = fmaf(xv.z, q1.z, m1); m1 = fmaf(xv.w, q1.w, m1);
                    m2 = fmaf(xv.x, q2.x, m2); m2 = fmaf(xv.y, q2.y, m2);
                    m2 = fmaf(xv.z, q2.z, m2); m2 = fmaf(xv.w, q2.w, m2);
                    m3 = fmaf(xv.x, q3.x, m3); m3 = fmaf(xv.y, q3.y, m3);
                    m3 = fmaf(xv.z, q3.z, m3); m3 = fmaf(xv.w, q3.w, m3);
                }
                float d0 = fmaf(-2.0f, m0, Sx + s_Se[k + 0]);
                float d1 = fmaf(-2.0f, m1, Sx + s_Se[k + 1]);
                float d2 = fmaf(-2.0f, m2, Sx + s_Se[k + 2]);
                float d3 = fmaf(-2.0f, m3, Sx + s_Se[k + 3]);
                if (d0 < best) { best = d0; bidx = k + 0; }
                if (d1 < best) { best = d1; bidx = k + 1; }
                if (d2 < best) { best = d2; bidx = k + 2; }
                if (d3 < best) { best = d3; bidx = k + 3; }
            }
        }
        s_win[tid] = bidx;
    }
    __syncthreads();

    // ================= output + loss (2 threads per row) ====================
    float rl = 0.0f;
    {
        const int r    = tid >> 1;
        const int half = (tid & 1) * (VQ_D / 2);
        const int row  = rowbase + r;
        const int win  = s_win[r];
        const float4* xp = reinterpret_cast<const float4*>(x + (size_t)row * VQ_D + half);
        const float4* qp = reinterpret_cast<const float4*>(cb + (size_t)win * VQ_D + half);
        float4* op = reinterpret_cast<float4*>(out + (size_t)row * VQ_D + half);
        #pragma unroll
        for (int i = 0; i < VQ_D / 8; i++) {
            float4 q = qp[i], xv = xp[i];
            float rx = q.x - xv.x, ry = q.y - xv.y, rz = q.z - xv.z, rw = q.w - xv.w;
            if (write_q) {
                float4 o; o.x = xv.x + rx; o.y = xv.y + ry; o.z = xv.z + rz; o.w = xv.w + rw;
                op[i] = o;
            }
            rl = fmaf(rx, rx, rl); rl = fmaf(ry, ry, rl);
            rl = fmaf(rz, rz, rl); rl = fmaf(rw, rw, rl);
        }
    }
    s_red[tid] = rl;
    __syncthreads();
    #pragma unroll
    for (int s = VQ_TPB / 2; s > 0; s >>= 1) {
        if (tid < s) s_red[tid] += s_red[tid + s];
        __syncthreads();
    }
    if (tid == 0) g_vq_partial[blockIdx.x] = s_red[0];
}

__global__ void vq_loss_kernel(float* __restrict__ out, int out_size)
{
    __shared__ double sd[VQ_TPB];
    const int tid = threadIdx.x;
    double acc = 0.0;
    for (int i = tid; i < VQ_GRID; i += VQ_TPB) acc += (double)g_vq_partial[i];
    sd[tid] = acc;
    __syncthreads();
    #pragma unroll
    for (int s = VQ_TPB / 2; s > 0; s >>= 1) {
        if (tid < s) sd[tid] += sd[tid + s];
        __syncthreads();
    }
    if (tid == 0) {
        double m = sd[0] / (double)((size_t)VQ_N * VQ_D);
        float loss = (float)(1.25 * m);
        const long long nq = (long long)VQ_N * VQ_D;
        if (out_size > nq) {
            for (long long i = nq; i < out_size; i++) out[i] = loss;
        } else if (out_size < nq && out_size > 0) {
            out[0] = loss;
        }
    }
}

extern "C" void kernel_launch(void* const* d_in, const int* in_sizes, int n_in,
                              void* d_out, int out_size)
{
    const float* x  = (const float*)d_in[0];
    const float* cb = (const float*)d_in[1];
    float* out = (float*)d_out;

    const long long nq = (long long)VQ_N * VQ_D;
    int write_q = (out_size >= nq) ? 1 : 0;

    vq_main_kernel<<<VQ_GRID, VQ_TPB>>>(x, cb, out, write_q);
    vq_loss_kernel<<<1, VQ_TPB>>>(out, out_size);
}

// round 7
// speedup vs baseline: 1.7955x; 1.7955x over previous
#include <cuda_runtime.h>
#include <cuda_bf16.h>
#include <cstdint>

// VectorQuantizer: N=262144 rows, D=64, K=1024 codes, fp32.
//
// Round 7: single bf16 tensor-core sweep + per-(row, 32-code-group) minima
// (transposed, padded layout) + WARP-COOPERATIVE exact rescore.
// R6's 3x regression was warp-divergent thread-per-row group rescoring
// (warp executed ~24/32 group bodies = ~75% of a full rescan). Now: warp per
// row, lane per code, ballot-selected groups -> zero divergence.
//   - rescore arithmetic is the bit-exact reference-rounding emulation:
//     M = serial ascending-d fmaf chain, t = Sx + Se, d = fmaf(-2, M, t),
//     argmin strict < ascending k (lower index wins ties).

#define VQ_N       262144
#define VQ_D       64
#define VQ_K       1024
#define VQ_TPB     256
#define VQ_ROWS_PB 128                    // 8 warps x 16 rows
#define VQ_GRID    (VQ_N / VQ_ROWS_PB)   // 2048 blocks
#define VQ_CHUNK   128                   // codes staged per chunk
#define VQ_NCHUNK  (VQ_K / VQ_CHUNK)     // 8
#define VQ_EPAD    72                    // padded bf16 row (144B)
#define VQ_GRP     32                    // codes per group (== warp size)
#define VQ_NGRP    (VQ_K / VQ_GRP)       // 32 groups (== warp size)
#define VQ_MARGIN  1e-3f

__device__ float g_vq_partial[VQ_GRID];

__device__ __forceinline__ uint32_t pack_bf16x2(float lo, float hi) {
    __nv_bfloat162 h = __float22bfloat162_rn(make_float2(lo, hi));
    return *reinterpret_cast<uint32_t*>(&h);
}

__device__ __forceinline__ void mma_bf16(float& c0, float& c1, float& c2, float& c3,
                                         uint32_t a0, uint32_t a1, uint32_t a2, uint32_t a3,
                                         uint32_t b0, uint32_t b1) {
    asm volatile(
        "mma.sync.aligned.m16n8k16.row.col.f32.bf16.bf16.f32 "
        "{%0,%1,%2,%3},{%4,%5,%6,%7},{%8,%9},{%0,%1,%2,%3};"
        : "+f"(c0), "+f"(c1), "+f"(c2), "+f"(c3)
        : "r"(a0), "r"(a1), "r"(a2), "r"(a3), "r"(b0), "r"(b1));
}

__device__ __forceinline__ void ldsm_x4(uint32_t& r0, uint32_t& r1, uint32_t& r2, uint32_t& r3,
                                        uint32_t addr) {
    asm volatile("ldmatrix.sync.aligned.m8n8.x4.shared.b16 {%0,%1,%2,%3}, [%4];"
                 : "=r"(r0), "=r"(r1), "=r"(r2), "=r"(r3) : "r"(addr));
}

__global__ void __launch_bounds__(VQ_TPB, 2)
vq_main_kernel(const float* __restrict__ x,
               const float* __restrict__ cb,
               float* __restrict__ out,
               int write_q)
{
    __shared__ __nv_bfloat16 s_e[VQ_CHUNK * VQ_EPAD];       // 18 KB bf16 chunk
    __shared__ float s_Se[VQ_K];                            // exact serial-fmaf norms
    __shared__ float s_gmin[VQ_NGRP][VQ_ROWS_PB + 1];       // transposed + padded
    __shared__ int   s_win[VQ_ROWS_PB];
    __shared__ float s_red[VQ_TPB];

    const int tid  = threadIdx.x;
    const int wid  = tid >> 5;
    const int lane = tid & 31;
    const int g    = lane >> 2;
    const int tg   = lane & 3;
    const int rowbase = blockIdx.x * VQ_ROWS_PB;
    const int r0i = wid * 16 + g;
    const int r1i = r0i + 8;

    // ---- exact Se (serial ascending fmaf; must match rescore arithmetic) ----
    #pragma unroll
    for (int c = 0; c < VQ_K / VQ_TPB; c++) {
        int code = tid + c * VQ_TPB;
        const float4* e4 = reinterpret_cast<const float4*>(cb + (size_t)code * VQ_D);
        float s = 0.0f;
        #pragma unroll
        for (int i = 0; i < VQ_D / 4; i++) {
            float4 q = e4[i];
            s = fmaf(q.x, q.x, s); s = fmaf(q.y, q.y, s);
            s = fmaf(q.z, q.z, s); s = fmaf(q.w, q.w, s);
        }
        s_Se[code] = s;
    }

    // ---- A fragments: warp's 16 rows (g, g+8) as bf16, kept in regs ----
    uint32_t afr[4][4];
    {
        const float* xr0 = x + (size_t)(rowbase + r0i) * VQ_D;
        const float* xr1 = xr0 + 8 * VQ_D;
        #pragma unroll
        for (int kt = 0; kt < 4; kt++) {
            int c = kt * 16 + 2 * tg;
            afr[kt][0] = pack_bf16x2(xr0[c],     xr0[c + 1]);
            afr[kt][1] = pack_bf16x2(xr1[c],     xr1[c + 1]);
            afr[kt][2] = pack_bf16x2(xr0[c + 8], xr0[c + 9]);
            afr[kt][3] = pack_bf16x2(xr1[c + 8], xr1[c + 9]);
        }
    }

    const uint32_t s_e_base = (uint32_t)__cvta_generic_to_shared(s_e);
    const uint32_t lds_lane = (uint32_t)((lane & 7) * VQ_EPAD * 2 + (lane >> 3) * 16);

    // ================= SINGLE SWEEP: gemm + group minima =================
    for (int ch = 0; ch < VQ_NCHUNK; ch++) {
        const int c0 = ch * VQ_CHUNK;
        __syncthreads();
        {   // stage chunk as bf16 (code tid/2, half (tid&1)*32)
            int code = (tid >> 1), half = (tid & 1) * 32;
            const float4* src = reinterpret_cast<const float4*>(
                cb + (size_t)(c0 + code) * VQ_D + half);
            uint32_t* dst = reinterpret_cast<uint32_t*>(s_e + code * VQ_EPAD + half);
            #pragma unroll
            for (int i = 0; i < 8; i++) {
                float4 v = src[i];
                dst[2 * i]     = pack_bf16x2(v.x, v.y);
                dst[2 * i + 1] = pack_bf16x2(v.z, v.w);
            }
        }
        __syncthreads();

        #pragma unroll
        for (int q = 0; q < VQ_CHUNK / VQ_GRP; q++) {     // 4 groups per chunk
            float gm0 = 3.0e38f, gm1 = 3.0e38f;
            #pragma unroll
            for (int j = 0; j < 4; j++) {                 // 4 n-tiles per group
                const int nt = q * 4 + j;
                uint32_t base = s_e_base + (uint32_t)(nt * 8 * VQ_EPAD * 2) + lds_lane;
                uint32_t b0, b1, b2, b3, b4, b5, b6, b7;
                ldsm_x4(b0, b1, b2, b3, base);
                ldsm_x4(b4, b5, b6, b7, base + 64);
                float cA0 = 0.f, cA1 = 0.f, cA2 = 0.f, cA3 = 0.f;
                float cB0 = 0.f, cB1 = 0.f, cB2 = 0.f, cB3 = 0.f;
                mma_bf16(cA0, cA1, cA2, cA3, afr[0][0], afr[0][1], afr[0][2], afr[0][3], b0, b1);
                mma_bf16(cB0, cB1, cB2, cB3, afr[2][0], afr[2][1], afr[2][2], afr[2][3], b4, b5);
                mma_bf16(cA0, cA1, cA2, cA3, afr[1][0], afr[1][1], afr[1][2], afr[1][3], b2, b3);
                mma_bf16(cB0, cB1, cB2, cB3, afr[3][0], afr[3][1], afr[3][2], afr[3][3], b6, b7);
                float2 se = *reinterpret_cast<const float2*>(&s_Se[c0 + nt * 8 + 2 * tg]);
                float d0 = fmaf(-2.f, cA0, fmaf(-2.f, cB0, se.x));
                float d1 = fmaf(-2.f, cA1, fmaf(-2.f, cB1, se.y));
                float d2 = fmaf(-2.f, cA2, fmaf(-2.f, cB2, se.x));
                float d3 = fmaf(-2.f, cA3, fmaf(-2.f, cB3, se.y));
                gm0 = fminf(gm0, fminf(d0, d1));
                gm1 = fminf(gm1, fminf(d2, d3));
            }
            // reduce group min across the 4 tg-lanes of each row
            gm0 = fminf(gm0, __shfl_xor_sync(0xffffffffu, gm0, 1));
            gm0 = fminf(gm0, __shfl_xor_sync(0xffffffffu, gm0, 2));
            gm1 = fminf(gm1, __shfl_xor_sync(0xffffffffu, gm1, 1));
            gm1 = fminf(gm1, __shfl_xor_sync(0xffffffffu, gm1, 2));
            if (tg == 0) {
                const int grp = ch * 4 + q;
                s_gmin[grp][r0i] = gm0;
                s_gmin[grp][r1i] = gm1;
            }
        }
    }
    __syncthreads();

    // ======== warp-cooperative exact rescore: warp per row, lane per code ======
    {
        const unsigned full = 0xffffffffu;
        #pragma unroll 1
        for (int rr = 0; rr < 16; rr++) {
            const int r   = wid * 16 + rr;
            const int row = rowbase + r;
            // lane l holds group l's fast min (conflict-free: padded layout)
            float gm = s_gmin[lane][r];
            float rowmin = gm;
            #pragma unroll
            for (int o = 16; o > 0; o >>= 1)
                rowmin = fminf(rowmin, __shfl_xor_sync(full, rowmin, o));
            const float thr = rowmin + VQ_MARGIN;
            unsigned mask = __ballot_sync(full, gm <= thr);

            // x row (broadcast loads) + exact Sx (serial ascending fmaf)
            float4 xr[VQ_D / 4];
            const float4* xp = reinterpret_cast<const float4*>(x + (size_t)row * VQ_D);
            float Sx = 0.0f;
            #pragma unroll
            for (int i = 0; i < VQ_D / 4; i++) {
                float4 v = xp[i];
                xr[i] = v;
                Sx = fmaf(v.x, v.x, Sx); Sx = fmaf(v.y, v.y, Sx);
                Sx = fmaf(v.z, v.z, Sx); Sx = fmaf(v.w, v.w, Sx);
            }

            float best = 3.0e38f;
            int   bidx = VQ_K;
            while (mask) {
                const int grp = __ffs(mask) - 1;
                mask &= mask - 1;
                const int k = grp * VQ_GRP + lane;       // lane's code
                const float4* e4 = reinterpret_cast<const float4*>(cb + (size_t)k * VQ_D);
                float m = 0.0f;
                #pragma unroll
                for (int i = 0; i < VQ_D / 4; i++) {
                    float4 q = e4[i], xv = xr[i];
                    m = fmaf(xv.x, q.x, m); m = fmaf(xv.y, q.y, m);
                    m = fmaf(xv.z, q.z, m); m = fmaf(xv.w, q.w, m);
                }
                float d = fmaf(-2.0f, m, Sx + s_Se[k]);
                if (d < best || (d == best && k < bidx)) { best = d; bidx = k; }
            }
            // warp argmin reduce, lower index wins ties
            #pragma unroll
            for (int o = 16; o > 0; o >>= 1) {
                float od = __shfl_xor_sync(full, best, o);
                int   oi = __shfl_xor_sync(full, bidx, o);
                if (od < best || (od == best && oi < bidx)) { best = od; bidx = oi; }
            }
            if (lane == 0) s_win[r] = bidx;
        }
    }
    __syncthreads();

    // ================= output + loss (2 threads per row) ====================
    float rl = 0.0f;
    {
        const int r    = tid >> 1;
        const int half = (tid & 1) * (VQ_D / 2);
        const int row  = rowbase + r;
        const int win  = s_win[r];
        const float4* xp = reinterpret_cast<const float4*>(x + (size_t)row * VQ_D + half);
        const float4* qp = reinterpret_cast<const float4*>(cb + (size_t)win * VQ_D + half);
        float4* op = reinterpret_cast<float4*>(out + (size_t)row * VQ_D + half);
        #pragma unroll
        for (int i = 0; i < VQ_D / 8; i++) {
            float4 q = qp[i], xv = xp[i];
            float rx = q.x - xv.x, ry = q.y - xv.y, rz = q.z - xv.z, rw = q.w - xv.w;
            if (write_q) {
                float4 o; o.x = xv.x + rx; o.y = xv.y + ry; o.z = xv.z + rz; o.w = xv.w + rw;
                op[i] = o;
            }
            rl = fmaf(rx, rx, rl); rl = fmaf(ry, ry, rl);
            rl = fmaf(rz, rz, rl); rl = fmaf(rw, rw, rl);
        }
    }
    s_red[tid] = rl;
    __syncthreads();
    #pragma unroll
    for (int s = VQ_TPB / 2; s > 0; s >>= 1) {
        if (tid < s) s_red[tid] += s_red[tid + s];
        __syncthreads();
    }
    if (tid == 0) g_vq_partial[blockIdx.x] = s_red[0];
}

__global__ void vq_loss_kernel(float* __restrict__ out, int out_size)
{
    __shared__ double sd[VQ_TPB];
    const int tid = threadIdx.x;
    double acc = 0.0;
    for (int i = tid; i < VQ_GRID; i += VQ_TPB) acc += (double)g_vq_partial[i];
    sd[tid] = acc;
    __syncthreads();
    #pragma unroll
    for (int s = VQ_TPB / 2; s > 0; s >>= 1) {
        if (tid < s) sd[tid] += sd[tid + s];
        __syncthreads();
    }
    if (tid == 0) {
        double m = sd[0] / (double)((size_t)VQ_N * VQ_D);
        float loss = (float)(1.25 * m);
        const long long nq = (long long)VQ_N * VQ_D;
        if (out_size > nq) {
            for (long long i = nq; i < out_size; i++) out[i] = loss;
        } else if (out_size < nq && out_size > 0) {
            out[0] = loss;
        }
    }
}

extern "C" void kernel_launch(void* const* d_in, const int* in_sizes, int n_in,
                              void* d_out, int out_size)
{
    const float* x  = (const float*)d_in[0];
    const float* cb = (const float*)d_in[1];
    float* out = (float*)d_out;

    const long long nq = (long long)VQ_N * VQ_D;
    int write_q = (out_size >= nq) ? 1 : 0;

    vq_main_kernel<<<VQ_GRID, VQ_TPB>>>(x, cb, out, write_q);
    vq_loss_kernel<<<1, VQ_TPB>>>(out, out_size);
}

// round 8
// speedup vs baseline: 3.0679x; 1.7086x over previous
#include <cuda_runtime.h>
#include <cuda_bf16.h>
#include <cstdint>

// VectorQuantizer: N=262144 rows, D=64, K=1024 codes, fp32.
//
// Round 8: revert to the PROVEN R3 logic (two bf16 mma sweeps + per-row
// candidate lists + exact thread-per-row rescore; 747us baseline), with:
//   (1) whole bf16 codebook staged ONCE into 147KB dynamic smem
//       -> both sweeps are pure ldsm+mma streams, ~4 barriers total
//       (vs 16x stage/convert/2-sync in R3)
//   (2) period-4 launch pattern [pad, main, loss, pad] so ncu -s 5 -c 1
//       finally profiles vq_main_kernel (5 mod 4 == 1).
// Selection arithmetic is the validated bit-exact reference emulation:
//   M = serial ascending-d fmaf chain, t = Sx + Se, d = fmaf(-2, M, t),
//   argmin strict < ascending k (lower index wins ties).

#define VQ_N       262144
#define VQ_D       64
#define VQ_K       1024
#define VQ_TPB     256
#define VQ_ROWS_PB 128                    // 8 warps x 16 rows
#define VQ_GRID    (VQ_N / VQ_ROWS_PB)   // 2048 blocks
#define VQ_CHUNK   128
#define VQ_NCHUNK  (VQ_K / VQ_CHUNK)     // 8
#define VQ_EPAD    72                    // padded bf16 row (144B)
#define VQ_SLOTS   16
#define VQ_MARGIN  1e-3f

#define VQ_SMEM_E  (VQ_K * VQ_EPAD * 2)  // 147456 bytes dynamic smem

__device__ float g_vq_partial[VQ_GRID];
__device__ int   g_vq_pad_sink;

__device__ __forceinline__ uint32_t pack_bf16x2(float lo, float hi) {
    __nv_bfloat162 h = __float22bfloat162_rn(make_float2(lo, hi));
    return *reinterpret_cast<uint32_t*>(&h);
}

__device__ __forceinline__ void mma_bf16(float& c0, float& c1, float& c2, float& c3,
                                         uint32_t a0, uint32_t a1, uint32_t a2, uint32_t a3,
                                         uint32_t b0, uint32_t b1) {
    asm volatile(
        "mma.sync.aligned.m16n8k16.row.col.f32.bf16.bf16.f32 "
        "{%0,%1,%2,%3},{%4,%5,%6,%7},{%8,%9},{%0,%1,%2,%3};"
        : "+f"(c0), "+f"(c1), "+f"(c2), "+f"(c3)
        : "r"(a0), "r"(a1), "r"(a2), "r"(a3), "r"(b0), "r"(b1));
}

__device__ __forceinline__ void ldsm_x4(uint32_t& r0, uint32_t& r1, uint32_t& r2, uint32_t& r3,
                                        uint32_t addr) {
    asm volatile("ldmatrix.sync.aligned.m8n8.x4.shared.b16 {%0,%1,%2,%3}, [%4];"
                 : "=r"(r0), "=r"(r1), "=r"(r2), "=r"(r3) : "r"(addr));
}

__device__ __forceinline__ float exact_dist(const float4* __restrict__ xr, float Sx,
                                            const float* __restrict__ cb,
                                            const float* __restrict__ se, int idx) {
    const float4* e4 = reinterpret_cast<const float4*>(cb + (size_t)idx * VQ_D);
    float m = 0.0f;
    #pragma unroll
    for (int i = 0; i < VQ_D / 4; i++) {
        float4 q = e4[i], xv = xr[i];
        m = fmaf(xv.x, q.x, m); m = fmaf(xv.y, q.y, m);
        m = fmaf(xv.z, q.z, m); m = fmaf(xv.w, q.w, m);
    }
    float t = Sx + se[idx];
    return fmaf(-2.0f, m, t);
}

extern __shared__ __nv_bfloat16 s_e[];   // [VQ_K][VQ_EPAD], 147456 B

__global__ void __launch_bounds__(VQ_TPB, 1)
vq_main_kernel(const float* __restrict__ x,
               const float* __restrict__ cb,
               float* __restrict__ out,
               int write_q)
{
    __shared__ float s_Se[VQ_K];
    __shared__ float s_rowmin[VQ_ROWS_PB];
    __shared__ int   s_cnt[VQ_ROWS_PB];
    __shared__ int   s_cand[VQ_ROWS_PB][VQ_SLOTS];
    __shared__ int   s_win[VQ_ROWS_PB];
    __shared__ float s_red[VQ_TPB];

    const int tid  = threadIdx.x;
    const int wid  = tid >> 5;
    const int lane = tid & 31;
    const int g    = lane >> 2;
    const int tg   = lane & 3;
    const int rowbase = blockIdx.x * VQ_ROWS_PB;
    const int r0i = wid * 16 + g;
    const int r1i = r0i + 8;

    // ---- stage ENTIRE codebook once: bf16 into dynamic smem + exact Se ----
    #pragma unroll
    for (int pass = 0; pass < VQ_K / 128; pass++) {       // 8 passes, no syncs
        int code = (tid >> 1) + pass * 128, half = (tid & 1) * 32;
        const float4* src = reinterpret_cast<const float4*>(
            cb + (size_t)code * VQ_D + half);
        uint32_t* dst = reinterpret_cast<uint32_t*>(s_e + code * VQ_EPAD + half);
        #pragma unroll
        for (int i = 0; i < 8; i++) {
            float4 v = src[i];
            dst[2 * i]     = pack_bf16x2(v.x, v.y);
            dst[2 * i + 1] = pack_bf16x2(v.z, v.w);
        }
    }
    #pragma unroll
    for (int c = 0; c < VQ_K / VQ_TPB; c++) {             // exact serial-fmaf norms
        int code = tid + c * VQ_TPB;
        const float4* e4 = reinterpret_cast<const float4*>(cb + (size_t)code * VQ_D);
        float s = 0.0f;
        #pragma unroll
        for (int i = 0; i < VQ_D / 4; i++) {
            float4 q = e4[i];
            s = fmaf(q.x, q.x, s); s = fmaf(q.y, q.y, s);
            s = fmaf(q.z, q.z, s); s = fmaf(q.w, q.w, s);
        }
        s_Se[code] = s;
    }
    if (tid < VQ_ROWS_PB) s_cnt[tid] = 0;

    // ---- A fragments: warp's 16 rows (g, g+8) as bf16, kept in regs ----
    uint32_t afr[4][4];
    {
        const float* xr0 = x + (size_t)(rowbase + r0i) * VQ_D;
        const float* xr1 = xr0 + 8 * VQ_D;
        #pragma unroll
        for (int kt = 0; kt < 4; kt++) {
            int c = kt * 16 + 2 * tg;
            afr[kt][0] = pack_bf16x2(xr0[c],     xr0[c + 1]);
            afr[kt][1] = pack_bf16x2(xr1[c],     xr1[c + 1]);
            afr[kt][2] = pack_bf16x2(xr0[c + 8], xr0[c + 9]);
            afr[kt][3] = pack_bf16x2(xr1[c + 8], xr1[c + 9]);
        }
    }

    const uint32_t s_e_base = (uint32_t)__cvta_generic_to_shared(s_e);
    const uint32_t lds_lane = (uint32_t)((lane & 7) * VQ_EPAD * 2 + (lane >> 3) * 16);

    __syncthreads();    // codebook staged

    // ================= SWEEP A: per-row fast min (pure mma stream) ==========
    float minr0 = 3.0e38f, minr1 = 3.0e38f;
    #pragma unroll 2
    for (int nt = 0; nt < VQ_K / 8; nt++) {               // 128 n-tiles
        uint32_t base = s_e_base + (uint32_t)(nt * 8 * VQ_EPAD * 2) + lds_lane;
        uint32_t b0, b1, b2, b3, b4, b5, b6, b7;
        ldsm_x4(b0, b1, b2, b3, base);
        ldsm_x4(b4, b5, b6, b7, base + 64);
        float cA0 = 0.f, cA1 = 0.f, cA2 = 0.f, cA3 = 0.f;
        float cB0 = 0.f, cB1 = 0.f, cB2 = 0.f, cB3 = 0.f;
        mma_bf16(cA0, cA1, cA2, cA3, afr[0][0], afr[0][1], afr[0][2], afr[0][3], b0, b1);
        mma_bf16(cB0, cB1, cB2, cB3, afr[2][0], afr[2][1], afr[2][2], afr[2][3], b4, b5);
        mma_bf16(cA0, cA1, cA2, cA3, afr[1][0], afr[1][1], afr[1][2], afr[1][3], b2, b3);
        mma_bf16(cB0, cB1, cB2, cB3, afr[3][0], afr[3][1], afr[3][2], afr[3][3], b6, b7);
        float2 se = *reinterpret_cast<const float2*>(&s_Se[nt * 8 + 2 * tg]);
        float d0 = fmaf(-2.f, cA0, fmaf(-2.f, cB0, se.x));
        float d1 = fmaf(-2.f, cA1, fmaf(-2.f, cB1, se.y));
        float d2 = fmaf(-2.f, cA2, fmaf(-2.f, cB2, se.x));
        float d3 = fmaf(-2.f, cA3, fmaf(-2.f, cB3, se.y));
        minr0 = fminf(minr0, fminf(d0, d1));
        minr1 = fminf(minr1, fminf(d2, d3));
    }
    minr0 = fminf(minr0, __shfl_xor_sync(0xffffffffu, minr0, 1));
    minr0 = fminf(minr0, __shfl_xor_sync(0xffffffffu, minr0, 2));
    minr1 = fminf(minr1, __shfl_xor_sync(0xffffffffu, minr1, 1));
    minr1 = fminf(minr1, __shfl_xor_sync(0xffffffffu, minr1, 2));
    if (tg == 0) {
        s_rowmin[r0i] = minr0;
        s_rowmin[r1i] = minr1;
    }
    __syncthreads();

    const float thr0 = s_rowmin[r0i] + VQ_MARGIN;
    const float thr1 = s_rowmin[r1i] + VQ_MARGIN;

    // ================= SWEEP B: collect candidates ==========================
    #pragma unroll 2
    for (int nt = 0; nt < VQ_K / 8; nt++) {
        uint32_t base = s_e_base + (uint32_t)(nt * 8 * VQ_EPAD * 2) + lds_lane;
        uint32_t b0, b1, b2, b3, b4, b5, b6, b7;
        ldsm_x4(b0, b1, b2, b3, base);
        ldsm_x4(b4, b5, b6, b7, base + 64);
        float cA0 = 0.f, cA1 = 0.f, cA2 = 0.f, cA3 = 0.f;
        float cB0 = 0.f, cB1 = 0.f, cB2 = 0.f, cB3 = 0.f;
        mma_bf16(cA0, cA1, cA2, cA3, afr[0][0], afr[0][1], afr[0][2], afr[0][3], b0, b1);
        mma_bf16(cB0, cB1, cB2, cB3, afr[2][0], afr[2][1], afr[2][2], afr[2][3], b4, b5);
        mma_bf16(cA0, cA1, cA2, cA3, afr[1][0], afr[1][1], afr[1][2], afr[1][3], b2, b3);
        mma_bf16(cB0, cB1, cB2, cB3, afr[3][0], afr[3][1], afr[3][2], afr[3][3], b6, b7);
        float2 se = *reinterpret_cast<const float2*>(&s_Se[nt * 8 + 2 * tg]);
        float d0 = fmaf(-2.f, cA0, fmaf(-2.f, cB0, se.x));
        float d1 = fmaf(-2.f, cA1, fmaf(-2.f, cB1, se.y));
        float d2 = fmaf(-2.f, cA2, fmaf(-2.f, cB2, se.x));
        float d3 = fmaf(-2.f, cA3, fmaf(-2.f, cB3, se.y));
        int codeb = nt * 8 + 2 * tg;
        if (d0 <= thr0) { int s = atomicAdd(&s_cnt[r0i], 1); if (s < VQ_SLOTS) s_cand[r0i][s] = codeb; }
        if (d1 <= thr0) { int s = atomicAdd(&s_cnt[r0i], 1); if (s < VQ_SLOTS) s_cand[r0i][s] = codeb + 1; }
        if (d2 <= thr1) { int s = atomicAdd(&s_cnt[r1i], 1); if (s < VQ_SLOTS) s_cand[r1i][s] = codeb; }
        if (d3 <= thr1) { int s = atomicAdd(&s_cnt[r1i], 1); if (s < VQ_SLOTS) s_cand[r1i][s] = codeb + 1; }
    }
    __syncthreads();

    // ================= exact rescore (threads 0..127, one row each) =========
    if (tid < VQ_ROWS_PB) {
        const int row = rowbase + tid;
        float4 xr[VQ_D / 4];
        const float4* xp = reinterpret_cast<const float4*>(x + (size_t)row * VQ_D);
        float Sx = 0.0f;
        #pragma unroll
        for (int i = 0; i < VQ_D / 4; i++) {
            float4 v = xp[i];
            xr[i] = v;
            Sx = fmaf(v.x, v.x, Sx); Sx = fmaf(v.y, v.y, Sx);
            Sx = fmaf(v.z, v.z, Sx); Sx = fmaf(v.w, v.w, Sx);
        }
        int   cnt  = s_cnt[tid];
        float best = 3.0e38f;
        int   bidx = VQ_K;
        if (cnt > VQ_SLOTS || cnt == 0) {
            for (int k = 0; k < VQ_K; k++) {              // statistically never
                float d = exact_dist(xr, Sx, cb, s_Se, k);
                if (d < best) { best = d; bidx = k; }
            }
        } else {
            for (int s = 0; s < cnt; s++) {
                int k = s_cand[tid][s];
                float d = exact_dist(xr, Sx, cb, s_Se, k);
                if (d < best || (d == best && k < bidx)) { best = d; bidx = k; }
            }
        }
        s_win[tid] = bidx;
    }
    __syncthreads();

    // ================= output + loss (2 threads per row) ====================
    float rl = 0.0f;
    {
        const int r    = tid >> 1;
        const int half = (tid & 1) * (VQ_D / 2);
        const int row  = rowbase + r;
        const int win  = s_win[r];
        const float4* xp = reinterpret_cast<const float4*>(x + (size_t)row * VQ_D + half);
        const float4* qp = reinterpret_cast<const float4*>(cb + (size_t)win * VQ_D + half);
        float4* op = reinterpret_cast<float4*>(out + (size_t)row * VQ_D + half);
        #pragma unroll
        for (int i = 0; i < VQ_D / 8; i++) {
            float4 q = qp[i], xv = xp[i];
            float rx = q.x - xv.x, ry = q.y - xv.y, rz = q.z - xv.z, rw = q.w - xv.w;
            if (write_q) {
                float4 o; o.x = xv.x + rx; o.y = xv.y + ry; o.z = xv.z + rz; o.w = xv.w + rw;
                op[i] = o;
            }
            rl = fmaf(rx, rx, rl); rl = fmaf(ry, ry, rl);
            rl = fmaf(rz, rz, rl); rl = fmaf(rw, rw, rl);
        }
    }
    s_red[tid] = rl;
    __syncthreads();
    #pragma unroll
    for (int s = VQ_TPB / 2; s > 0; s >>= 1) {
        if (tid < s) s_red[tid] += s_red[tid + s];
        __syncthreads();
    }
    if (tid == 0) g_vq_partial[blockIdx.x] = s_red[0];
}

__global__ void vq_loss_kernel(float* __restrict__ out, int out_size)
{
    __shared__ double sd[VQ_TPB];
    const int tid = threadIdx.x;
    double acc = 0.0;
    for (int i = tid; i < VQ_GRID; i += VQ_TPB) acc += (double)g_vq_partial[i];
    sd[tid] = acc;
    __syncthreads();
    #pragma unroll
    for (int s = VQ_TPB / 2; s > 0; s >>= 1) {
        if (tid < s) sd[tid] += sd[tid + s];
        __syncthreads();
    }
    if (tid == 0) {
        double m = sd[0] / (double)((size_t)VQ_N * VQ_D);
        float loss = (float)(1.25 * m);
        const long long nq = (long long)VQ_N * VQ_D;
        if (out_size > nq) {
            for (long long i = nq; i < out_size; i++) out[i] = loss;
        } else if (out_size < nq && out_size > 0) {
            out[0] = loss;
        }
    }
}

// Tiny non-empty pad kernels: make the launch period 4 so ncu -s 5 -c 1
// (index 5, 5 mod 4 == 1) lands on vq_main_kernel.
__global__ void vq_pad_kernel() { if (threadIdx.x == 1024) g_vq_pad_sink = 1; }

extern "C" void kernel_launch(void* const* d_in, const int* in_sizes, int n_in,
                              void* d_out, int out_size)
{
    const float* x  = (const float*)d_in[0];
    const float* cb = (const float*)d_in[1];
    float* out = (float*)d_out;

    const long long nq = (long long)VQ_N * VQ_D;
    int write_q = (out_size >= nq) ? 1 : 0;

    static int smem_configured = 0;
    if (!smem_configured) {
        cudaFuncSetAttribute(vq_main_kernel,
                             cudaFuncAttributeMaxDynamicSharedMemorySize, VQ_SMEM_E);
        smem_configured = 1;
    }

    vq_pad_kernel<<<1, 32>>>();
    vq_main_kernel<<<VQ_GRID, VQ_TPB, VQ_SMEM_E>>>(x, cb, out, write_q);
    vq_loss_kernel<<<1, VQ_TPB>>>(out, out_size);
    vq_pad_kernel<<<1, 32>>>();
}